// round 3
// baseline (speedup 1.0000x reference)
#include <cuda_runtime.h>

#define BB 16
#define CL 512
#define QL 64
#define HH 768
#define NEG_INF (-1e30f)

// ---------------- scratch (static device arrays; no allocation) ----------------
__device__ __align__(16) float g_qp[BB * QL * HH];   // q @ W            [B,64,768]
__device__ __align__(16) float g_bq[BB * QL];        // q . b            [B,64]
__device__ __align__(16) float g_s [BB * CL * QL];   // logits           [B,512,64]
__device__ __align__(16) float g_s1[BB * CL * QL];   // row softmax      [B,512,64]
__device__ __align__(16) float g_s2[BB * CL * QL];   // col softmax      [B,512,64]
__device__ __align__(16) float g_t [BB * QL * HH];   // s2^T @ c         [B,64,768]

// ---------------- bq[row] = q[row,:] . b ----------------
__global__ void bq_kernel(const float* __restrict__ q, const float* __restrict__ bias) {
    int row  = blockIdx.x * 8 + (threadIdx.x >> 5);   // 1024 rows total
    int lane = threadIdx.x & 31;
    const float* qr = q + row * HH;
    float s = 0.f;
    for (int d = lane; d < HH; d += 32) s += qr[d] * bias[d];
#pragma unroll
    for (int o = 16; o; o >>= 1) s += __shfl_down_sync(0xffffffffu, s, o);
    if (lane == 0) g_bq[row] = s;
}

// ---------------- qp = q @ W   (M=1024, N=768, K=768) ----------------
__global__ void qp_gemm(const float* __restrict__ q, const float* __restrict__ W) {
    __shared__ float As[16][65];   // As[k][m]
    __shared__ float Bs[16][65];   // Bs[k][n]
    int tid = threadIdx.x;
    int tx = tid & 15, ty = tid >> 4;
    int tx4 = tx << 2, ty4 = ty << 2;
    int mBase = blockIdx.y * 64;
    int nBase = blockIdx.x * 64;
    int lm = tid >> 2;            // 0..63
    int lk = (tid & 3) << 2;      // 0,4,8,12
    int bk = tid >> 4;            // 0..15
    int bn = (tid & 15) << 2;     // 0..60
    float acc[4][4] = {};
    for (int kt = 0; kt < HH; kt += 16) {
        float4 av = *(const float4*)(q + (mBase + lm) * HH + kt + lk);
        As[lk + 0][lm] = av.x; As[lk + 1][lm] = av.y;
        As[lk + 2][lm] = av.z; As[lk + 3][lm] = av.w;
        float4 bv = *(const float4*)(W + (kt + bk) * HH + nBase + bn);
        Bs[bk][bn + 0] = bv.x; Bs[bk][bn + 1] = bv.y;
        Bs[bk][bn + 2] = bv.z; Bs[bk][bn + 3] = bv.w;
        __syncthreads();
#pragma unroll
        for (int k = 0; k < 16; k++) {
            float ar[4], br[4];
#pragma unroll
            for (int i = 0; i < 4; i++) ar[i] = As[k][ty4 + i];
#pragma unroll
            for (int j = 0; j < 4; j++) br[j] = Bs[k][tx4 + j];
#pragma unroll
            for (int i = 0; i < 4; i++)
#pragma unroll
                for (int j = 0; j < 4; j++) acc[i][j] = fmaf(ar[i], br[j], acc[i][j]);
        }
        __syncthreads();
    }
#pragma unroll
    for (int i = 0; i < 4; i++) {
        float4 o = make_float4(acc[i][0], acc[i][1], acc[i][2], acc[i][3]);
        *(float4*)(g_qp + (mBase + ty4 + i) * HH + nBase + tx4) = o;
    }
}

// ---------------- s[b,c,j] = sum_h c[b,c,h]*qp[b,j,h] + bq[b,j] ----------------
__global__ void s_gemm(const float* __restrict__ c) {
    __shared__ float As[16][65];   // As[k][m]   from c
    __shared__ float Bs[16][65];   // Bs[k][j]   from qp (K-major)
    int tid = threadIdx.x;
    int tx = tid & 15, ty = tid >> 4;
    int tx4 = tx << 2, ty4 = ty << 2;
    int b = blockIdx.y;
    int mBase = blockIdx.x * 64;
    const float* A = c + b * CL * HH;
    const float* Bt = g_qp + b * QL * HH;
    int lm = tid >> 2;
    int lk = (tid & 3) << 2;
    float acc[4][4] = {};
    for (int kt = 0; kt < HH; kt += 16) {
        float4 av = *(const float4*)(A + (mBase + lm) * HH + kt + lk);
        As[lk + 0][lm] = av.x; As[lk + 1][lm] = av.y;
        As[lk + 2][lm] = av.z; As[lk + 3][lm] = av.w;
        float4 bv = *(const float4*)(Bt + lm * HH + kt + lk);   // lm = j row (0..63)
        Bs[lk + 0][lm] = bv.x; Bs[lk + 1][lm] = bv.y;
        Bs[lk + 2][lm] = bv.z; Bs[lk + 3][lm] = bv.w;
        __syncthreads();
#pragma unroll
        for (int k = 0; k < 16; k++) {
            float ar[4], br[4];
#pragma unroll
            for (int i = 0; i < 4; i++) ar[i] = As[k][ty4 + i];
#pragma unroll
            for (int j = 0; j < 4; j++) br[j] = Bs[k][tx4 + j];
#pragma unroll
            for (int i = 0; i < 4; i++)
#pragma unroll
                for (int j = 0; j < 4; j++) acc[i][j] = fmaf(ar[i], br[j], acc[i][j]);
        }
        __syncthreads();
    }
#pragma unroll
    for (int i = 0; i < 4; i++) {
        float4 o;
        o.x = acc[i][0] + g_bq[b * QL + tx4 + 0];
        o.y = acc[i][1] + g_bq[b * QL + tx4 + 1];
        o.z = acc[i][2] + g_bq[b * QL + tx4 + 2];
        o.w = acc[i][3] + g_bq[b * QL + tx4 + 3];
        *(float4*)(g_s + (b * CL + mBase + ty4 + i) * QL + tx4) = o;
    }
}

// ---------------- s1: row softmax over j with q_mask ----------------
__global__ void row_softmax(const int* __restrict__ q_mask) {
    int row  = blockIdx.x * 8 + (threadIdx.x >> 5);   // 0..8191
    int lane = threadIdx.x & 31;
    int b = row >> 9;                                  // row / CL
    const float* sr = g_s + row * QL;
    int m0 = q_mask[b * QL + lane];
    int m1 = q_mask[b * QL + lane + 32];
    float v0 = m0 ? sr[lane]      : NEG_INF;
    float v1 = m1 ? sr[lane + 32] : NEG_INF;
    float mx = fmaxf(v0, v1);
#pragma unroll
    for (int o = 16; o; o >>= 1) mx = fmaxf(mx, __shfl_xor_sync(0xffffffffu, mx, o));
    float e0 = __expf(v0 - mx);
    float e1 = __expf(v1 - mx);
    float s = e0 + e1;
#pragma unroll
    for (int o = 16; o; o >>= 1) s += __shfl_xor_sync(0xffffffffu, s, o);
    float inv = 1.f / s;
    g_s1[row * QL + lane]      = e0 * inv;
    g_s1[row * QL + lane + 32] = e1 * inv;
}

// ---------------- s2: column softmax over c with c_mask ----------------
__global__ void col_softmax(const int* __restrict__ c_mask) {
    int j = blockIdx.x;       // 0..63
    int b = blockIdx.y;       // 0..15
    int t = threadIdx.x;      // 0..127
    int lane = t & 31, w = t >> 5;
    __shared__ float redm[4], reds[4];
    float v[4];
#pragma unroll
    for (int i = 0; i < 4; i++) {
        int crow = t + i * 128;
        v[i] = c_mask[b * CL + crow] ? g_s[(b * CL + crow) * QL + j] : NEG_INF;
    }
    float mx = fmaxf(fmaxf(v[0], v[1]), fmaxf(v[2], v[3]));
#pragma unroll
    for (int o = 16; o; o >>= 1) mx = fmaxf(mx, __shfl_xor_sync(0xffffffffu, mx, o));
    if (lane == 0) redm[w] = mx;
    __syncthreads();
    mx = fmaxf(fmaxf(redm[0], redm[1]), fmaxf(redm[2], redm[3]));
    float e[4]; float s = 0.f;
#pragma unroll
    for (int i = 0; i < 4; i++) { e[i] = __expf(v[i] - mx); s += e[i]; }
#pragma unroll
    for (int o = 16; o; o >>= 1) s += __shfl_xor_sync(0xffffffffu, s, o);
    if (lane == 0) reds[w] = s;
    __syncthreads();
    s = reds[0] + reds[1] + reds[2] + reds[3];
    float inv = 1.f / s;
#pragma unroll
    for (int i = 0; i < 4; i++)
        g_s2[(b * CL + t + i * 128) * QL + j] = e[i] * inv;
}

// ---------------- t[b,j,h] = sum_c s2[b,c,j] * c[b,c,h]  (M=64, N=768, K=512) ----------------
__global__ void t_gemm(const float* __restrict__ c) {
    __shared__ float As[16][65];   // As[kc][j]
    __shared__ float Bs[16][65];   // Bs[kc][h]
    int tid = threadIdx.x;
    int tx = tid & 15, ty = tid >> 4;
    int tx4 = tx << 2, ty4 = ty << 2;
    int b = blockIdx.y;
    int nBase = blockIdx.x * 64;
    int bk = tid >> 4;            // 0..15 (k row)
    int q4 = (tid & 15) << 2;     // 0..60
    float acc[4][4] = {};
    for (int kt = 0; kt < CL; kt += 16) {
        float4 av = *(const float4*)(g_s2 + (b * CL + kt + bk) * QL + q4);
        As[bk][q4 + 0] = av.x; As[bk][q4 + 1] = av.y;
        As[bk][q4 + 2] = av.z; As[bk][q4 + 3] = av.w;
        float4 bv = *(const float4*)(c + (b * CL + kt + bk) * HH + nBase + q4);
        Bs[bk][q4 + 0] = bv.x; Bs[bk][q4 + 1] = bv.y;
        Bs[bk][q4 + 2] = bv.z; Bs[bk][q4 + 3] = bv.w;
        __syncthreads();
#pragma unroll
        for (int k = 0; k < 16; k++) {
            float ar[4], br[4];
#pragma unroll
            for (int i = 0; i < 4; i++) ar[i] = As[k][ty4 + i];
#pragma unroll
            for (int j = 0; j < 4; j++) br[j] = Bs[k][tx4 + j];
#pragma unroll
            for (int i = 0; i < 4; i++)
#pragma unroll
                for (int j = 0; j < 4; j++) acc[i][j] = fmaf(ar[i], br[j], acc[i][j]);
        }
        __syncthreads();
    }
#pragma unroll
    for (int i = 0; i < 4; i++) {
        float4 o = make_float4(acc[i][0], acc[i][1], acc[i][2], acc[i][3]);
        *(float4*)(g_t + (b * QL + ty4 + i) * HH + nBase + tx4) = o;
    }
}

// ---------------- final: a = s1@q, bvec = s1@t, out = [c, a, c*a, c*bvec] ----------------
// grid (ctile=8, b=16, hhalf=2); block 256; tile 64 c-rows x 64 h per chunk, K=64 (full).
// FIX: 64-wide tiles need each thread to fill 16 floats (4 float4), not 4.
__global__ void final_kernel(const float* __restrict__ c, const float* __restrict__ q,
                             float* __restrict__ out) {
    __shared__ float S1s[64][65];  // [c][j]
    __shared__ float Buf[64][65];  // [j][h]  (q chunk then t chunk)
    int tid = threadIdx.x;
    int tx = tid & 15, ty = tid >> 4;
    int tx4 = tx << 2, ty4 = ty << 2;
    int b = blockIdx.y;
    int cBase = blockIdx.x * 64;
    int hStart = blockIdx.z * 384;

    int lr  = tid >> 2;            // 0..63  (row in tile)
    int lcb = (tid & 3) << 2;      // 0,4,8,12 (base col; +16*i covers 64)

    // load full 64x64 s1 tile
#pragma unroll
    for (int i = 0; i < 4; i++) {
        int lc = lcb + i * 16;
        float4 sv = *(const float4*)(g_s1 + (b * CL + cBase + lr) * QL + lc);
        S1s[lr][lc + 0] = sv.x; S1s[lr][lc + 1] = sv.y;
        S1s[lr][lc + 2] = sv.z; S1s[lr][lc + 3] = sv.w;
    }
    __syncthreads();

    const float* qb = q + b * QL * HH;
    const float* tb = g_t + b * QL * HH;
    const float* cb = c + b * CL * HH;
    float* ob = out + (size_t)(b * CL) * (4 * HH);

    for (int hc = hStart; hc < hStart + 384; hc += 64) {
        // ---- pass 1: a = s1 @ q ----
#pragma unroll
        for (int i = 0; i < 4; i++) {
            int lc = lcb + i * 16;
            float4 qv = *(const float4*)(qb + lr * HH + hc + lc);
            Buf[lr][lc + 0] = qv.x; Buf[lr][lc + 1] = qv.y;
            Buf[lr][lc + 2] = qv.z; Buf[lr][lc + 3] = qv.w;
        }
        __syncthreads();
        float acc[4][4] = {};
#pragma unroll 16
        for (int k = 0; k < 64; k++) {
            float ar[4], br[4];
#pragma unroll
            for (int i = 0; i < 4; i++) ar[i] = S1s[ty4 + i][k];
#pragma unroll
            for (int j = 0; j < 4; j++) br[j] = Buf[k][tx4 + j];
#pragma unroll
            for (int i = 0; i < 4; i++)
#pragma unroll
                for (int j = 0; j < 4; j++) acc[i][j] = fmaf(ar[i], br[j], acc[i][j]);
        }
#pragma unroll
        for (int i = 0; i < 4; i++) {
            int r = cBase + ty4 + i;
            float4 cv = *(const float4*)(cb + r * HH + hc + tx4);
            float4 a4 = make_float4(acc[i][0], acc[i][1], acc[i][2], acc[i][3]);
            float4 ca = make_float4(cv.x * a4.x, cv.y * a4.y, cv.z * a4.z, cv.w * a4.w);
            float* orow = ob + (size_t)r * (4 * HH);
            *(float4*)(orow + 0 * HH + hc + tx4) = cv;   // c
            *(float4*)(orow + 1 * HH + hc + tx4) = a4;   // a
            *(float4*)(orow + 2 * HH + hc + tx4) = ca;   // c*a
        }
        __syncthreads();
        // ---- pass 2: bvec = s1 @ t ----
#pragma unroll
        for (int i = 0; i < 4; i++) {
            int lc = lcb + i * 16;
            float4 tv = *(const float4*)(tb + lr * HH + hc + lc);
            Buf[lr][lc + 0] = tv.x; Buf[lr][lc + 1] = tv.y;
            Buf[lr][lc + 2] = tv.z; Buf[lr][lc + 3] = tv.w;
        }
        __syncthreads();
        float acc2[4][4] = {};
#pragma unroll 16
        for (int k = 0; k < 64; k++) {
            float ar[4], br[4];
#pragma unroll
            for (int i = 0; i < 4; i++) ar[i] = S1s[ty4 + i][k];
#pragma unroll
            for (int j = 0; j < 4; j++) br[j] = Buf[k][tx4 + j];
#pragma unroll
            for (int i = 0; i < 4; i++)
#pragma unroll
                for (int j = 0; j < 4; j++) acc2[i][j] = fmaf(ar[i], br[j], acc2[i][j]);
        }
#pragma unroll
        for (int i = 0; i < 4; i++) {
            int r = cBase + ty4 + i;
            float4 cv = *(const float4*)(cb + r * HH + hc + tx4);
            float4 cbv = make_float4(cv.x * acc2[i][0], cv.y * acc2[i][1],
                                     cv.z * acc2[i][2], cv.w * acc2[i][3]);
            float* orow = ob + (size_t)r * (4 * HH);
            *(float4*)(orow + 3 * HH + hc + tx4) = cbv;  // c*bvec
        }
        __syncthreads();
    }
}

extern "C" void kernel_launch(void* const* d_in, const int* in_sizes, int n_in,
                              void* d_out, int out_size) {
    (void)in_sizes; (void)n_in; (void)out_size;
    const float* c      = (const float*)d_in[0];
    const float* q      = (const float*)d_in[1];
    const int*   c_mask = (const int*)d_in[2];
    const int*   q_mask = (const int*)d_in[3];
    const float* W      = (const float*)d_in[4];
    const float* bias   = (const float*)d_in[5];
    float* out = (float*)d_out;

    bq_kernel   <<<128, 256>>>(q, bias);
    qp_gemm     <<<dim3(12, 16), 256>>>(q, W);
    s_gemm      <<<dim3(8, 16), 256>>>(c);
    row_softmax <<<1024, 256>>>(q_mask);
    col_softmax <<<dim3(64, 16), 128>>>(c_mask);
    t_gemm      <<<dim3(12, 16), 256>>>(c);
    final_kernel<<<dim3(8, 16, 2), 256>>>(c, q, out);
}